// round 1
// baseline (speedup 1.0000x reference)
#include <cuda_runtime.h>

// ---------------------------------------------------------------------------
// SpMiddleFHD: 2x submanifold 3x3x3 conv (128->16 relu, 16->16 relu) on a
// sparse point set, then strided (s=2,p=1) sparse conv 16->32 scattered into a
// dense (B,Do,Ho,Wo,32) grid with relu.
//
// Shapes (compile-time constants, fixed by the problem):
//   B=2, Dz=41, Hy=400, Wx=352, N=40000 points, Do=21, Ho=200, Wo=176.
// ---------------------------------------------------------------------------

namespace {
constexpr int kB  = 2;
constexpr int kDZ = 41, kHY = 400, kWX = 352;
constexpr int kGD = kDZ + 2, kGH = kHY + 2, kGW = kWX + 2;   // padded grid
constexpr int kN  = 40000;
constexpr int kDO = 21, kHO = 200, kWO = 176;
constexpr int kGridCells = kB * kGD * kGH * kGW;             // 12,238,488
}

// Scratch (static device globals; no allocation in kernel_launch).
__device__ __align__(16) int   g_grid[kGridCells];   // ~49 MB, idx or -1
__device__            int   g_nbr[27 * kN];          // neighbor table, [k][n]
__device__ __align__(16) float g_x1[kN * 16];
__device__ __align__(16) float g_x2[kN * 16];
__device__ __align__(16) float g_W1t[27 * 16 * 128]; // W1 transposed [k][d][c]

// ---------------------------------------------------------------------------
__global__ void k_fill_grid() {
    int i = blockIdx.x * blockDim.x + threadIdx.x;
    int n4 = kGridCells / 4;
    if (i < n4) reinterpret_cast<int4*>(g_grid)[i] = make_int4(-1, -1, -1, -1);
}

__global__ void k_zero_out(float4* __restrict__ out, int n4) {
    int i = blockIdx.x * blockDim.x + threadIdx.x;
    if (i < n4) out[i] = make_float4(0.f, 0.f, 0.f, 0.f);
}

__global__ void k_scatter_idx(const int* __restrict__ coors) {
    int n = blockIdx.x * blockDim.x + threadIdx.x;
    if (n >= kN) return;
    int b = coors[n * 4 + 0], z = coors[n * 4 + 1];
    int y = coors[n * 4 + 2], x = coors[n * 4 + 3];
    g_grid[((b * kGD + z + 1) * kGH + y + 1) * kGW + x + 1] = n;
}

__global__ void k_build_nbr(const int* __restrict__ coors) {
    int n = blockIdx.x * blockDim.x + threadIdx.x;
    if (n >= kN) return;
    int b = coors[n * 4 + 0], z = coors[n * 4 + 1];
    int y = coors[n * 4 + 2], x = coors[n * 4 + 3];
    #pragma unroll
    for (int k = 0; k < 27; k++) {
        int dk = k / 9, dy = (k / 3) % 3, dx = k % 3;
        // reference: nbr = grid[b, z+off0, y+off1, x+off2] with off in {0,1,2}
        g_nbr[k * kN + n] =
            g_grid[((b * kGD + z + dk) * kGH + y + dy) * kGW + x + dx];
    }
}

// W1 (27,128,16) -> W1t (27,16,128) so conv1 lanes read contiguous c.
__global__ void k_w1t(const float* __restrict__ W1) {
    int i = blockIdx.x * blockDim.x + threadIdx.x;
    if (i >= 27 * 128 * 16) return;
    int d = i & 15;
    int c = (i >> 4) & 127;
    int k = i >> 11;
    g_W1t[(k * 16 + d) * 128 + c] = W1[i];
}

// ---------------------------------------------------------------------------
// conv1: warp per point; lanes cover the 128 input channels as float4.
__global__ void k_conv1(const float* __restrict__ feat) {
    int n    = blockIdx.x * (blockDim.x >> 5) + (threadIdx.x >> 5);
    int lane = threadIdx.x & 31;
    if (n >= kN) return;

    float acc[16];
    #pragma unroll
    for (int d = 0; d < 16; d++) acc[d] = 0.f;

    const float4* fv = reinterpret_cast<const float4*>(feat);
    const float4* wv = reinterpret_cast<const float4*>(g_W1t);

    for (int k = 0; k < 27; k++) {
        int idx = g_nbr[k * kN + n];          // warp-uniform
        if (idx < 0) continue;                 // ~96% of iterations skip
        float4 f = __ldcg(&fv[idx * 32 + lane]);   // coalesced 512B gather, L2
        #pragma unroll
        for (int d = 0; d < 16; d++) {
            float4 w = __ldg(&wv[(k * 16 + d) * 32 + lane]);  // L1-hot
            acc[d] += f.x * w.x + f.y * w.y + f.z * w.z + f.w * w.w;
        }
    }

    // butterfly reduce each of the 16 accumulators across the warp
    float res = 0.f;
    #pragma unroll
    for (int d = 0; d < 16; d++) {
        float v = acc[d];
        v += __shfl_xor_sync(0xffffffffu, v, 16);
        v += __shfl_xor_sync(0xffffffffu, v, 8);
        v += __shfl_xor_sync(0xffffffffu, v, 4);
        v += __shfl_xor_sync(0xffffffffu, v, 2);
        v += __shfl_xor_sync(0xffffffffu, v, 1);
        if (lane == d) res = v;
    }
    if (lane < 16) g_x1[n * 16 + lane] = fmaxf(res, 0.f);  // relu
}

// ---------------------------------------------------------------------------
// conv2: thread per point. 16x16 weight per k read as broadcast float4s.
__global__ void k_conv2(const float4* __restrict__ W2v) {
    int n = blockIdx.x * blockDim.x + threadIdx.x;
    if (n >= kN) return;

    float4 a0 = make_float4(0,0,0,0), a1 = a0, a2 = a0, a3 = a0;

    for (int k = 0; k < 27; k++) {
        int idx = g_nbr[k * kN + n];
        if (idx < 0) continue;
        const float4* xr = reinterpret_cast<const float4*>(&g_x1[idx * 16]);
        float xs[16];
        *reinterpret_cast<float4*>(&xs[0])  = xr[0];
        *reinterpret_cast<float4*>(&xs[4])  = xr[1];
        *reinterpret_cast<float4*>(&xs[8])  = xr[2];
        *reinterpret_cast<float4*>(&xs[12]) = xr[3];
        #pragma unroll
        for (int c = 0; c < 16; c++) {
            float xc = xs[c];
            const float4* wr = &W2v[(k * 16 + c) * 4];
            float4 w0 = __ldg(wr + 0);
            float4 w1 = __ldg(wr + 1);
            float4 w2 = __ldg(wr + 2);
            float4 w3 = __ldg(wr + 3);
            a0.x += xc * w0.x; a0.y += xc * w0.y; a0.z += xc * w0.z; a0.w += xc * w0.w;
            a1.x += xc * w1.x; a1.y += xc * w1.y; a1.z += xc * w1.z; a1.w += xc * w1.w;
            a2.x += xc * w2.x; a2.y += xc * w2.y; a2.z += xc * w2.z; a2.w += xc * w2.w;
            a3.x += xc * w3.x; a3.y += xc * w3.y; a3.z += xc * w3.z; a3.w += xc * w3.w;
        }
    }

    float4* o = reinterpret_cast<float4*>(&g_x2[n * 16]);
    o[0] = make_float4(fmaxf(a0.x,0.f), fmaxf(a0.y,0.f), fmaxf(a0.z,0.f), fmaxf(a0.w,0.f));
    o[1] = make_float4(fmaxf(a1.x,0.f), fmaxf(a1.y,0.f), fmaxf(a1.z,0.f), fmaxf(a1.w,0.f));
    o[2] = make_float4(fmaxf(a2.x,0.f), fmaxf(a2.y,0.f), fmaxf(a2.z,0.f), fmaxf(a2.w,0.f));
    o[3] = make_float4(fmaxf(a3.x,0.f), fmaxf(a3.y,0.f), fmaxf(a3.z,0.f), fmaxf(a3.w,0.f));
}

// ---------------------------------------------------------------------------
// conv3 + strided scatter: warp per point, lane = output channel (32).
// Each point touches at most 8 (avg 3.375) downsampled voxels, each with a
// unique kernel offset k. Scatter via per-lane atomicAdd (coalesced line).
__global__ void k_conv3_scatter(const int* __restrict__ coors,
                                const float* __restrict__ W3,
                                float* __restrict__ out) {
    int n    = blockIdx.x * (blockDim.x >> 5) + (threadIdx.x >> 5);
    int lane = threadIdx.x & 31;
    if (n >= kN) return;

    int b = coors[n * 4 + 0], z = coors[n * 4 + 1];
    int y = coors[n * 4 + 2], x = coors[n * 4 + 3];

    float xs[16];
    #pragma unroll
    for (int c = 0; c < 16; c++) xs[c] = g_x2[n * 16 + c];  // broadcast

    for (int dk = 0; dk < 3; dk++) {
        int oz = z + 1 - dk;
        if (oz < 0 || (oz & 1)) continue;
        int pz = oz >> 1;
        if (pz >= kDO) continue;
        for (int dy = 0; dy < 3; dy++) {
            int oy = y + 1 - dy;
            if (oy < 0 || (oy & 1)) continue;
            int py = oy >> 1;
            if (py >= kHO) continue;
            for (int dx = 0; dx < 3; dx++) {
                int ox = x + 1 - dx;
                if (ox < 0 || (ox & 1)) continue;
                int px = ox >> 1;
                if (px >= kWO) continue;
                int k    = dk * 9 + dy * 3 + dx;
                int base = ((b * kDO + pz) * kHO + py) * kWO + px;
                float v = 0.f;
                #pragma unroll
                for (int c = 0; c < 16; c++)
                    v += xs[c] * __ldg(&W3[(k * 16 + c) * 32 + lane]);
                atomicAdd(&out[base * 32 + lane], v);
            }
        }
    }
}

// Idempotent relu over exactly the touched voxels (duplicates benign).
__global__ void k_relu_touched(const int* __restrict__ coors,
                               float* __restrict__ out) {
    int n    = blockIdx.x * (blockDim.x >> 5) + (threadIdx.x >> 5);
    int lane = threadIdx.x & 31;
    if (n >= kN) return;

    int b = coors[n * 4 + 0], z = coors[n * 4 + 1];
    int y = coors[n * 4 + 2], x = coors[n * 4 + 3];

    for (int dk = 0; dk < 3; dk++) {
        int oz = z + 1 - dk;
        if (oz < 0 || (oz & 1)) continue;
        int pz = oz >> 1;
        if (pz >= kDO) continue;
        for (int dy = 0; dy < 3; dy++) {
            int oy = y + 1 - dy;
            if (oy < 0 || (oy & 1)) continue;
            int py = oy >> 1;
            if (py >= kHO) continue;
            for (int dx = 0; dx < 3; dx++) {
                int ox = x + 1 - dx;
                if (ox < 0 || (ox & 1)) continue;
                int px = ox >> 1;
                if (px >= kWO) continue;
                int base = ((b * kDO + pz) * kHO + py) * kWO + px;
                int o = base * 32 + lane;
                out[o] = fmaxf(out[o], 0.f);
            }
        }
    }
}

// ---------------------------------------------------------------------------
extern "C" void kernel_launch(void* const* d_in, const int* in_sizes, int n_in,
                              void* d_out, int out_size) {
    const float* feat  = (const float*)d_in[0];   // (40000,128) f32
    const int*   coors = (const int*)  d_in[1];   // (40000,4)   i32
    const float* W1    = (const float*)d_in[2];   // (3,3,3,128,16)
    const float* W2    = (const float*)d_in[3];   // (3,3,3,16,16)
    const float* W3    = (const float*)d_in[4];   // (3,3,3,16,32)
    float*       out   = (float*)d_out;           // (2,21,200,176,32)
    (void)in_sizes; (void)n_in;

    const int n4_grid = kGridCells / 4;
    const int n4_out  = out_size / 4;

    k_fill_grid   <<<(n4_grid + 255) / 256, 256>>>();
    k_zero_out    <<<(n4_out  + 255) / 256, 256>>>((float4*)out, n4_out);
    k_scatter_idx <<<(kN + 255) / 256, 256>>>(coors);
    k_w1t         <<<(27 * 128 * 16 + 255) / 256, 256>>>(W1);
    k_build_nbr   <<<(kN + 255) / 256, 256>>>(coors);
    k_conv1       <<<(kN + 7) / 8, 256>>>(feat);
    k_conv2       <<<(kN + 255) / 256, 256>>>((const float4*)W2);
    k_conv3_scatter<<<(kN + 7) / 8, 256>>>(coors, W3, out);
    k_relu_touched <<<(kN + 7) / 8, 256>>>(coors, out);
}

// round 2
// speedup vs baseline: 1.0512x; 1.0512x over previous
#include <cuda_runtime.h>

// ---------------------------------------------------------------------------
// SpMiddleFHD: subm3x3x3 conv 128->16 relu, subm 16->16 relu, strided (s=2,p=1)
// conv 16->32 scattered into dense (B,Do,Ho,Wo,32) with relu.
// B=2, Dz=41, Hy=400, Wx=352, N=40000, Do=21, Ho=200, Wo=176.
//
// Grid hash uses idx+1 in uint16 (0 = empty). Static device globals are
// zero-initialized at load; after the last grid reader each call, the 40000
// touched cells are cleared back to 0, preserving the invariant across graph
// replays without a 24.5MB fill pass.
// ---------------------------------------------------------------------------

namespace {
constexpr int kB  = 2;
constexpr int kDZ = 41, kHY = 400, kWX = 352;
constexpr int kGD = kDZ + 2, kGH = kHY + 2, kGW = kWX + 2;
constexpr int kN  = 40000;
constexpr int kDO = 21, kHO = 200, kWO = 176;
constexpr int kGridCells = kB * kGD * kGH * kGW;  // 12,238,488
}

__device__ unsigned short g_grid[kGridCells];     // 24.5 MB, idx+1 (0 empty)
__device__ int   g_cnt[kN];                       // valid-neighbor count
__device__ int   g_list[kN * 27];                 // packed (k<<16)|idx
__device__ __align__(16) float g_x1[kN * 16];
__device__ __align__(16) float g_x2[kN * 16];

__device__ __forceinline__ int cell_of(int4 c, int dk, int dy, int dx) {
    return ((c.x * kGD + c.y + dk) * kGH + c.z + dy) * kGW + c.w + dx;
}

// ---------------------------------------------------------------------------
__global__ void k_scatter(const int4* __restrict__ coors) {
    int n = blockIdx.x * blockDim.x + threadIdx.x;
    if (n >= kN) return;
    int4 c = __ldg(&coors[n]);
    g_grid[cell_of(c, 1, 1, 1)] = (unsigned short)(n + 1);
}

// ---------------------------------------------------------------------------
// conv1 (128->16, relu) fused with neighbor-table construction.
// Warp per point. Lanes 0..26 probe the 27 grid cells in parallel, ballot,
// and write the compacted (k,idx) list for conv2. Then the warp iterates only
// the valid entries (avg ~1.09), lanes covering 128 input channels as float4.
__global__ void k_conv1(const float* __restrict__ feat,
                        const int4* __restrict__ coors,
                        const float* __restrict__ W1) {
    int n    = blockIdx.x * (blockDim.x >> 5) + (threadIdx.x >> 5);
    int lane = threadIdx.x & 31;
    if (n >= kN) return;

    int4 c = __ldg(&coors[n]);

    int v = -1;
    if (lane < 27) {
        int dk = lane / 9, dy = (lane / 3) % 3, dx = lane % 3;
        v = (int)g_grid[cell_of(c, dk, dy, dx)] - 1;
    }
    unsigned ball = __ballot_sync(0xffffffffu, v >= 0);
    int pre = __popc(ball & ((1u << lane) - 1));
    if (v >= 0) g_list[n * 27 + pre] = (lane << 16) | v;
    if (lane == 0) g_cnt[n] = __popc(ball);

    float4 a0 = make_float4(0,0,0,0), a1 = a0, a2 = a0, a3 = a0;
    const float4* fv = reinterpret_cast<const float4*>(feat);
    const float4* wv = reinterpret_cast<const float4*>(W1);  // (27,128,4xfloat4)

    for (unsigned m = ball; m; m &= m - 1) {
        int k   = __ffs(m) - 1;
        int idx = __shfl_sync(0xffffffffu, v, k);
        float4 f = __ldcg(&fv[idx * 32 + lane]);       // 4 channels per lane
        const float4* wk = &wv[(k * 128 + lane * 4) * 4];
        float4 w;
        w = __ldg(wk + 0);  a0.x+=f.x*w.x; a0.y+=f.x*w.y; a0.z+=f.x*w.z; a0.w+=f.x*w.w;
        w = __ldg(wk + 1);  a1.x+=f.x*w.x; a1.y+=f.x*w.y; a1.z+=f.x*w.z; a1.w+=f.x*w.w;
        w = __ldg(wk + 2);  a2.x+=f.x*w.x; a2.y+=f.x*w.y; a2.z+=f.x*w.z; a2.w+=f.x*w.w;
        w = __ldg(wk + 3);  a3.x+=f.x*w.x; a3.y+=f.x*w.y; a3.z+=f.x*w.z; a3.w+=f.x*w.w;
        w = __ldg(wk + 4);  a0.x+=f.y*w.x; a0.y+=f.y*w.y; a0.z+=f.y*w.z; a0.w+=f.y*w.w;
        w = __ldg(wk + 5);  a1.x+=f.y*w.x; a1.y+=f.y*w.y; a1.z+=f.y*w.z; a1.w+=f.y*w.w;
        w = __ldg(wk + 6);  a2.x+=f.y*w.x; a2.y+=f.y*w.y; a2.z+=f.y*w.z; a2.w+=f.y*w.w;
        w = __ldg(wk + 7);  a3.x+=f.y*w.x; a3.y+=f.y*w.y; a3.z+=f.y*w.z; a3.w+=f.y*w.w;
        w = __ldg(wk + 8);  a0.x+=f.z*w.x; a0.y+=f.z*w.y; a0.z+=f.z*w.z; a0.w+=f.z*w.w;
        w = __ldg(wk + 9);  a1.x+=f.z*w.x; a1.y+=f.z*w.y; a1.z+=f.z*w.z; a1.w+=f.z*w.w;
        w = __ldg(wk + 10); a2.x+=f.z*w.x; a2.y+=f.z*w.y; a2.z+=f.z*w.z; a2.w+=f.z*w.w;
        w = __ldg(wk + 11); a3.x+=f.z*w.x; a3.y+=f.z*w.y; a3.z+=f.z*w.z; a3.w+=f.z*w.w;
        w = __ldg(wk + 12); a0.x+=f.w*w.x; a0.y+=f.w*w.y; a0.z+=f.w*w.z; a0.w+=f.w*w.w;
        w = __ldg(wk + 13); a1.x+=f.w*w.x; a1.y+=f.w*w.y; a1.z+=f.w*w.z; a1.w+=f.w*w.w;
        w = __ldg(wk + 14); a2.x+=f.w*w.x; a2.y+=f.w*w.y; a2.z+=f.w*w.z; a2.w+=f.w*w.w;
        w = __ldg(wk + 15); a3.x+=f.w*w.x; a3.y+=f.w*w.y; a3.z+=f.w*w.z; a3.w+=f.w*w.w;
    }

    // Reduce 16 partial sums (one per output channel) across the warp.
    float vals[16] = {a0.x,a0.y,a0.z,a0.w, a1.x,a1.y,a1.z,a1.w,
                      a2.x,a2.y,a2.z,a2.w, a3.x,a3.y,a3.z,a3.w};
    float res = 0.f;
    #pragma unroll
    for (int d = 0; d < 16; d++) {
        float t = vals[d];
        t += __shfl_xor_sync(0xffffffffu, t, 16);
        t += __shfl_xor_sync(0xffffffffu, t, 8);
        t += __shfl_xor_sync(0xffffffffu, t, 4);
        t += __shfl_xor_sync(0xffffffffu, t, 2);
        t += __shfl_xor_sync(0xffffffffu, t, 1);
        if (lane == d) res = t;
    }
    if (lane < 16) g_x1[n * 16 + lane] = fmaxf(res, 0.f);
}

// ---------------------------------------------------------------------------
// conv2 (16->16, relu) via compact list; also clears this point's grid cell
// (conv1 was the last grid reader), restoring the all-zero invariant.
__global__ void k_conv2(const float4* __restrict__ W2v,
                        const int4* __restrict__ coors) {
    int n = blockIdx.x * blockDim.x + threadIdx.x;
    if (n >= kN) return;

    int cnt = g_cnt[n];
    float4 a0 = make_float4(0,0,0,0), a1 = a0, a2 = a0, a3 = a0;

    for (int j = 0; j < cnt; j++) {
        int p   = g_list[n * 27 + j];
        int idx = p & 0xffff;
        int k   = p >> 16;
        const float4* xr = reinterpret_cast<const float4*>(&g_x1[idx * 16]);
        float xs[16];
        *reinterpret_cast<float4*>(&xs[0])  = xr[0];
        *reinterpret_cast<float4*>(&xs[4])  = xr[1];
        *reinterpret_cast<float4*>(&xs[8])  = xr[2];
        *reinterpret_cast<float4*>(&xs[12]) = xr[3];
        #pragma unroll
        for (int cc = 0; cc < 16; cc++) {
            float xc = xs[cc];
            const float4* wr = &W2v[(k * 16 + cc) * 4];
            float4 w0 = __ldg(wr + 0), w1 = __ldg(wr + 1);
            float4 w2 = __ldg(wr + 2), w3 = __ldg(wr + 3);
            a0.x+=xc*w0.x; a0.y+=xc*w0.y; a0.z+=xc*w0.z; a0.w+=xc*w0.w;
            a1.x+=xc*w1.x; a1.y+=xc*w1.y; a1.z+=xc*w1.z; a1.w+=xc*w1.w;
            a2.x+=xc*w2.x; a2.y+=xc*w2.y; a2.z+=xc*w2.z; a2.w+=xc*w2.w;
            a3.x+=xc*w3.x; a3.y+=xc*w3.y; a3.z+=xc*w3.z; a3.w+=xc*w3.w;
        }
    }

    float4* o = reinterpret_cast<float4*>(&g_x2[n * 16]);
    o[0] = make_float4(fmaxf(a0.x,0.f), fmaxf(a0.y,0.f), fmaxf(a0.z,0.f), fmaxf(a0.w,0.f));
    o[1] = make_float4(fmaxf(a1.x,0.f), fmaxf(a1.y,0.f), fmaxf(a1.z,0.f), fmaxf(a1.w,0.f));
    o[2] = make_float4(fmaxf(a2.x,0.f), fmaxf(a2.y,0.f), fmaxf(a2.z,0.f), fmaxf(a2.w,0.f));
    o[3] = make_float4(fmaxf(a3.x,0.f), fmaxf(a3.y,0.f), fmaxf(a3.z,0.f), fmaxf(a3.w,0.f));

    // restore grid to all-zero for the next replay
    int4 c = __ldg(&coors[n]);
    g_grid[cell_of(c, 1, 1, 1)] = 0;
}

// ---------------------------------------------------------------------------
// conv3 (16->32) + strided scatter. Warp per point, lane = output channel.
__global__ void k_conv3_scatter(const int4* __restrict__ coors,
                                const float* __restrict__ W3,
                                float* __restrict__ out) {
    int n    = blockIdx.x * (blockDim.x >> 5) + (threadIdx.x >> 5);
    int lane = threadIdx.x & 31;
    if (n >= kN) return;

    int4 c = __ldg(&coors[n]);
    float xs[16];
    #pragma unroll
    for (int cc = 0; cc < 16; cc++) xs[cc] = g_x2[n * 16 + cc];

    for (int dk = 0; dk < 3; dk++) {
        int oz = c.y + 1 - dk;
        if (oz < 0 || (oz & 1)) continue;
        int pz = oz >> 1;
        if (pz >= kDO) continue;
        for (int dy = 0; dy < 3; dy++) {
            int oy = c.z + 1 - dy;
            if (oy < 0 || (oy & 1)) continue;
            int py = oy >> 1;
            if (py >= kHO) continue;
            for (int dx = 0; dx < 3; dx++) {
                int ox = c.w + 1 - dx;
                if (ox < 0 || (ox & 1)) continue;
                int px = ox >> 1;
                if (px >= kWO) continue;
                int k    = dk * 9 + dy * 3 + dx;
                int base = ((c.x * kDO + pz) * kHO + py) * kWO + px;
                float v = 0.f;
                #pragma unroll
                for (int cc = 0; cc < 16; cc++)
                    v += xs[cc] * __ldg(&W3[(k * 16 + cc) * 32 + lane]);
                atomicAdd(&out[base * 32 + lane], v);
            }
        }
    }
}

// Idempotent relu over exactly the touched voxels (duplicates benign).
__global__ void k_relu_touched(const int4* __restrict__ coors,
                               float* __restrict__ out) {
    int n    = blockIdx.x * (blockDim.x >> 5) + (threadIdx.x >> 5);
    int lane = threadIdx.x & 31;
    if (n >= kN) return;

    int4 c = __ldg(&coors[n]);
    for (int dk = 0; dk < 3; dk++) {
        int oz = c.y + 1 - dk;
        if (oz < 0 || (oz & 1)) continue;
        int pz = oz >> 1;
        if (pz >= kDO) continue;
        for (int dy = 0; dy < 3; dy++) {
            int oy = c.z + 1 - dy;
            if (oy < 0 || (oy & 1)) continue;
            int py = oy >> 1;
            if (py >= kHO) continue;
            for (int dx = 0; dx < 3; dx++) {
                int ox = c.w + 1 - dx;
                if (ox < 0 || (ox & 1)) continue;
                int px = ox >> 1;
                if (px >= kWO) continue;
                int base = ((c.x * kDO + pz) * kHO + py) * kWO + px;
                int o = base * 32 + lane;
                out[o] = fmaxf(out[o], 0.f);
            }
        }
    }
}

// ---------------------------------------------------------------------------
extern "C" void kernel_launch(void* const* d_in, const int* in_sizes, int n_in,
                              void* d_out, int out_size) {
    const float* feat  = (const float*)d_in[0];
    const int4*  coors = (const int4*) d_in[1];
    const float* W1    = (const float*)d_in[2];
    const float* W2    = (const float*)d_in[3];
    const float* W3    = (const float*)d_in[4];
    float*       out   = (float*)d_out;
    (void)in_sizes; (void)n_in;

    cudaMemsetAsync(out, 0, (size_t)out_size * sizeof(float), 0);
    k_scatter       <<<(kN + 255) / 256, 256>>>(coors);
    k_conv1         <<<(kN + 7) / 8, 256>>>(feat, coors, W1);
    k_conv2         <<<(kN + 255) / 256, 256>>>((const float4*)W2, coors);
    k_conv3_scatter <<<(kN + 7) / 8, 256>>>(coors, W3, out);
    k_relu_touched  <<<(kN + 7) / 8, 256>>>(coors, out);
}